// round 14
// baseline (speedup 1.0000x reference)
#include <cuda_runtime.h>
#include <cuda_fp16.h>
#include <mma.h>
#include <math.h>

using namespace nvcuda;

#define Bq   64
#define Pq   196
#define EDq  2048
#define ADq  512
#define DDq  512
#define Eq   300
#define Vq   1000
#define VPAD 1024
#define Tq   96
#define TD   95
#define KCAT 2860   // (E + ED) + DD = 2348 + 512
#define KPAD 2864   // KCAT padded to multiple of 16
#define G4   2048   // 4*DD
#define HP   2560   // ADq + EDq (fused att2|gate width)
#define NBLK 296
#define HSL  8      // hproj K-slices

// output layout (flattened fp32, reference-return order)
#define OUT_PRED    0LL
#define OUT_CAPS    6080000LL
#define OUT_DECLEN  6086144LL
#define OUT_ALPHAS  6086208LL
#define OUT_SORTIND 7277888LL

// ---------------- scratch ----------------
__device__ int   g_sortind[Bq];
__device__ int   g_declen[Bq];
__device__ int   g_caps[Bq * Tq];
__device__ __half g_eosh[(long long)Bq * Pq * EDq];      // fp16 sorted eo (~51MB)
__device__ float g_att1f[(long long)Bq * Pq * ADq];      // fp32 att1 staging (setup)
__device__ __half g_att1h[(long long)Bq * Pq * ADq];     // fp16 att1 + bias (loop)
__device__ float g_meaneo[Bq * EDq];
__device__ float g_h[Bq * DDq];
__device__ __half g_hh[Bq * DDq];                        // fp16 h (wmma A operand)
__device__ float g_c[Bq * DDq];
__device__ __half g_xcath[Bq * KPAD];                    // fp16 [emb | gate*awe | h | 0pad]
__device__ __half g_wcath[(long long)KPAD * G4];         // fp16 gates W, INTERLEAVED cols (d*4+gate)
__device__ __half g_whcatH[(long long)DDq * HP];         // fp16 [W_dec_att | W_fbeta]
__device__ __half g_weah[(long long)EDq * ADq];          // fp16 W_enc_att
__device__ __half g_wfch[(long long)DDq * VPAD];         // fp16 W_fc, cols padded to 1024
__device__ float g_biasg[G4];                            // (b_ih + b_hh), interleaved
__device__ float g_part[16LL * Bq * DDq];                // setup split-K scratch
__device__ float g_partH[(long long)HSL * Bq * HP];      // hproj slices
__device__ float g_partP[4LL * Bq * VPAD];               // preds slices
__device__ float g_partG[9LL * Bq * G4];                 // gates slices (interleaved cols)
__device__ float g_awepart[2LL * Bq * EDq];              // awe p-split partials
__device__ unsigned g_barcnt;                            // zero-init, monotonic
__device__ unsigned g_cntG[16];                          // gates n-tile arrival counters
__device__ unsigned g_cntA[Bq];                          // awe pair arrival counters

__device__ __forceinline__ float sigf(float x) { return 1.0f / (1.0f + expf(-x)); }

// ---------------- grid barrier (monotonic counter; nanosleep backoff poll) ----------------
__device__ __forceinline__ void gridbar()
{
    __syncthreads();
    if (threadIdx.x == 0) {
        asm volatile("fence.acq_rel.gpu;" ::: "memory");
        unsigned old = atomicAdd(&g_barcnt, 1u);
        unsigned target = old - (old % (unsigned)NBLK) + (unsigned)NBLK;
        unsigned cur;
        while (true) {
            asm volatile("ld.acquire.gpu.u32 %0, [%1];" : "=r"(cur) : "l"(&g_barcnt));
            if ((int)(cur - target) >= 0) break;
            __nanosleep(200);
        }
    }
    __syncthreads();
}

// =============== setup kernel 1: sort + all weight conversions ===============
__global__ void k_prep(const int* __restrict__ lens, const int* __restrict__ caps,
                       float* __restrict__ out,
                       const float* __restrict__ Wih, const float* __restrict__ Whh,
                       const float* __restrict__ bih, const float* __restrict__ bhh,
                       const float* __restrict__ Wda, const float* __restrict__ Wfb,
                       const float* __restrict__ Wea, const float* __restrict__ Wfc)
{
    if (blockIdx.x == 0) {
        int i = threadIdx.x;
        if (i < Bq) {
            int li = lens[i];
            int r = 0;
            for (int j = 0; j < Bq; j++) {
                int lj = lens[j];
                if (lj > li || (lj == li && j < i)) r++;
            }
            g_sortind[r] = i;
        }
        __syncthreads();
        if (i < Bq) {
            int src = g_sortind[i];
            int dl = lens[src] - 1;
            g_declen[i] = dl;
            out[OUT_DECLEN + i]  = (float)dl;
            out[OUT_SORTIND + i] = (float)src;
            for (int tt = 0; tt < Tq; tt++) {
                int v = caps[src * Tq + tt];
                g_caps[i * Tq + tt] = v;
                out[OUT_CAPS + i * Tq + tt] = (float)v;
            }
        }
    }
    long long idx = (long long)blockIdx.x * blockDim.x + threadIdx.x;
    long long n1 = (long long)KCAT * G4;
    long long n2 = (long long)DDq * HP;
    long long n3 = (long long)EDq * ADq;
    long long n4 = (long long)DDq * VPAD;
    if (idx < n1) {
        int row = (int)(idx / G4), ncol = (int)(idx % G4);
        int d = ncol >> 2, gate = ncol & 3;
        int scol = gate * 512 + d;
        float v = (row < 2348) ? Wih[(long long)row * G4 + scol]
                               : Whh[(long long)(row - 2348) * G4 + scol];
        g_wcath[idx] = __float2half(v);
    } else if (idx < n1 + n2) {
        long long idx2 = idx - n1;
        int row = (int)(idx2 / HP), col = (int)(idx2 % HP);
        float v = (col < ADq) ? Wda[(long long)row * ADq + col]
                              : Wfb[(long long)row * EDq + (col - ADq)];
        g_whcatH[idx2] = __float2half(v);
    } else if (idx < n1 + n2 + n3) {
        long long idx3 = idx - n1 - n2;
        g_weah[idx3] = __float2half(Wea[idx3]);
    } else if (idx < n1 + n2 + n3 + n4) {
        long long idx4 = idx - n1 - n2 - n3;
        int row = (int)(idx4 >> 10), col = (int)(idx4 & (VPAD - 1));
        float v = (col < Vq) ? Wfc[(long long)row * Vq + col] : 0.0f;
        g_wfch[idx4] = __float2half(v);
    }
    if (idx < G4) {
        int d = (int)(idx >> 2), gate = (int)(idx & 3);
        int scol = gate * 512 + d;
        g_biasg[idx] = bih[scol] + bhh[scol];
    }
}

// =============== setup kernel 2: gather encoder_out (sorted, fp16) ===============
__global__ void k_gather(const float* __restrict__ eo)
{
    int bp = blockIdx.x;
    int b = bp / Pq, p = bp % Pq;
    int src = g_sortind[b];
    const float4* s = (const float4*)(eo + ((long long)(src * Pq + p)) * EDq);
    __half2* dh = (__half2*)(g_eosh + (long long)bp * EDq);
    for (int i = threadIdx.x; i < EDq / 4; i += blockDim.x) {
        float4 v = s[i];
        dh[i * 2]     = __floats2half2_rn(v.x, v.y);
        dh[i * 2 + 1] = __floats2half2_rn(v.z, v.w);
    }
}

// ---------------- fp16 wmma GEMM device: C[64, col0:+128] = A @ B ----------------
__device__ __forceinline__ void gemm_wmma(const __half* __restrict__ A, int lda,
    const __half* __restrict__ B, int ldb, float* __restrict__ C, int ldc,
    int col0, int k0, int k1, float* SHf)
{
    __half* As = (__half*)SHf;          // [64][16]
    __half* Bs = As + 64 * 16;          // [16][128]
    int tid = threadIdx.x;
    int wid = tid >> 5;
    int mt = wid >> 1;
    int nh = (wid & 1) * 64;

    wmma::fragment<wmma::accumulator, 16, 16, 16, float> acc[4];
#pragma unroll
    for (int j = 0; j < 4; j++) wmma::fill_fragment(acc[j], 0.0f);

    int arow = tid >> 1;
    int acol8 = (tid & 1) * 8;
    int bk = tid >> 4;
    int bn8 = (tid & 15) * 8;

    uint4 pa, pb;
    if (tid < 128) pa = *(const uint4*)&A[(long long)arow * lda + k0 + acol8];
    pb = *(const uint4*)&B[(long long)(k0 + bk) * ldb + col0 + bn8];

    for (int kb = k0; kb < k1; kb += 16) {
        if (tid < 128) *(uint4*)&As[arow * 16 + acol8] = pa;
        *(uint4*)&Bs[bk * 128 + bn8] = pb;
        __syncthreads();

        int kn = kb + 16;
        if (kn < k1) {
            if (tid < 128) pa = *(const uint4*)&A[(long long)arow * lda + kn + acol8];
            pb = *(const uint4*)&B[(long long)(kn + bk) * ldb + col0 + bn8];
        }

        wmma::fragment<wmma::matrix_a, 16, 16, 16, __half, wmma::row_major> af;
        wmma::load_matrix_sync(af, As + mt * 16 * 16, 16);
#pragma unroll
        for (int j = 0; j < 4; j++) {
            wmma::fragment<wmma::matrix_b, 16, 16, 16, __half, wmma::row_major> bf;
            wmma::load_matrix_sync(bf, Bs + nh + j * 16, 128);
            wmma::mma_sync(acc[j], af, bf, acc[j]);
        }
        __syncthreads();
    }

#pragma unroll
    for (int j = 0; j < 4; j++)
        wmma::store_matrix_sync(C + (long long)(mt * 16) * ldc + col0 + nh + j * 16,
                                acc[j], ldc, wmma::mem_row_major);
}

// ---------------- fp32 64x128 GEMM device (h0/c0 setup only) ----------------
__device__ __forceinline__ void gemm64x128(const float* __restrict__ A, int lda,
    const float* __restrict__ B, int ldb, float* __restrict__ C, int ldc,
    int col0, int N, int k0, int k1, float* SH)
{
    float* As = SH;
    float* Bs = SH + 1024;
    int tid = threadIdx.x;
    int tx = tid & 31, ty = tid >> 5;
    float acc[8][4] = {};

    int am  = tid & 63;
    int akq = (tid >> 6) << 2;
    int bkk0 = tid >> 5;
    int bkk1 = bkk0 + 8;
    int bn   = (tid & 31) << 2;

    for (int kb = k0; kb < k1; kb += 16) {
        {
            int kg = kb + akq;
            float4 pa = *(const float4*)&A[(long long)am * lda + kg];
            As[(akq + 0) * 64 + am] = pa.x;
            As[(akq + 1) * 64 + am] = pa.y;
            As[(akq + 2) * 64 + am] = pa.z;
            As[(akq + 3) * 64 + am] = pa.w;
            int kgb0 = kb + bkk0, kgb1 = kb + bkk1, ng = col0 + bn;
            float4 pb0 = make_float4(0.f,0.f,0.f,0.f), pb1 = make_float4(0.f,0.f,0.f,0.f);
            if (ng + 3 < N) {
                pb0 = *(const float4*)&B[(long long)kgb0 * ldb + ng];
                pb1 = *(const float4*)&B[(long long)kgb1 * ldb + ng];
            } else {
                for (int j = 0; j < 4; j++) if (ng + j < N) {
                    ((float*)&pb0)[j] = B[(long long)kgb0 * ldb + ng + j];
                    ((float*)&pb1)[j] = B[(long long)kgb1 * ldb + ng + j];
                }
            }
            *(float4*)&Bs[bkk0 * 128 + bn] = pb0;
            *(float4*)&Bs[bkk1 * 128 + bn] = pb1;
        }
        __syncthreads();
#pragma unroll
        for (int kk = 0; kk < 16; kk++) {
            float a0[4], a1[4], bb[4];
            *(float4*)&a0[0] = *(const float4*)&As[kk * 64 + ty * 8];
            *(float4*)&a1[0] = *(const float4*)&As[kk * 64 + ty * 8 + 4];
            *(float4*)&bb[0] = *(const float4*)&Bs[kk * 128 + tx * 4];
#pragma unroll
            for (int i = 0; i < 4; i++)
#pragma unroll
                for (int j = 0; j < 4; j++) {
                    acc[i][j]     += a0[i] * bb[j];
                    acc[i + 4][j] += a1[i] * bb[j];
                }
        }
        __syncthreads();
    }

#pragma unroll
    for (int i = 0; i < 8; i++) {
        int m = ty * 8 + i;
#pragma unroll
        for (int j = 0; j < 4; j++) {
            int n = col0 + tx * 4 + j;
            if (n < N) C[(long long)m * ldc + n] = acc[i][j];
        }
    }
}

// =============== setup kernel 3: mean, h0/c0, att1 (persistent) ===============
__global__ void __launch_bounds__(256, 2)
k_setup2(const float* __restrict__ Wih0, const float* __restrict__ bih0,
         const float* __restrict__ Wic0, const float* __restrict__ bic0,
         const float* __restrict__ bea)
{
    __shared__ float SH[3072];
    int bid = blockIdx.x;
    int tid = threadIdx.x;

    // phase a: mean over P
    for (int task = bid; task < 512; task += NBLK) {
        int b = task >> 3, chunk = task & 7;
        int e = chunk * 256 + tid;
        float s = 0.0f;
        const __half* base = g_eosh + (long long)b * Pq * EDq + e;
        for (int p = 0; p < Pq; p++) s += __half2float(base[(long long)p * EDq]);
        g_meaneo[b * EDq + e] = s * (1.0f / (float)Pq);
    }
    gridbar();

    // phase b: att1 wmma tiles (784) + h0/c0 fp32 split-K tiles (64)
    for (int task = bid; task < 784 + 64; task += NBLK) {
        if (task < 784) {
            int mrow = task >> 2, nt = task & 3;
            gemm_wmma(g_eosh + (long long)mrow * 64 * EDq, EDq, g_weah, ADq,
                      g_att1f + (long long)mrow * 64 * ADq, ADq, nt * 128, 0, EDq, SH);
        } else {
            int t2 = task - 784;
            int w = t2 >> 5;
            int s = (t2 >> 2) & 7;
            int nt = t2 & 3;
            const float* W = w ? Wic0 : Wih0;
            gemm64x128(g_meaneo, EDq, W, DDq,
                       g_part + (long long)(w * 8 + s) * Bq * DDq, DDq,
                       nt * 128, DDq, s * 256, s * 256 + 256, SH);
        }
    }
    gridbar();

    // phase c: reduce h0/c0 + att1h convert
    for (long long idx = (long long)bid * 256 + tid; idx < 2LL * Bq * DDq;
         idx += (long long)NBLK * 256) {
        int w = (int)(idx >> 15);
        int i = (int)(idx & 32767);
        int n = i & (DDq - 1);
        float v = w ? bic0[n] : bih0[n];
#pragma unroll
        for (int s = 0; s < 8; s++) v += g_part[(long long)(w * 8 + s) * Bq * DDq + i];
        if (w == 0) { g_h[i] = v; g_hh[i] = __float2half(v); }
        else g_c[i] = v;
    }
    for (long long i = (long long)bid * 256 + tid; i < (long long)Bq * Pq * ADq;
         i += (long long)NBLK * 256)
        g_att1h[i] = __float2half(g_att1f[i] + bea[i & (ADq - 1)]);
}

// ================= persistent loop kernel =================

// fused attention + p-split awe; 2 blocks per batch
__device__ void attn_awe_pair(int bid, int t, const float* __restrict__ wfull,
                              const float* __restrict__ bfull,
                              const float* __restrict__ bda,
                              const float* __restrict__ bfb,
                              float* __restrict__ out, float* SH,
                              unsigned* s_last)
{
    int b = bid >> 1, hv = bid & 1;
    float* sh_att2 = SH;
    float* sh_w    = SH + 512;
    float* sh_e    = SH + 1024;
    float* red     = SH + 1248;
    int tid = threadIdx.x;

    for (int i = tid; i < ADq; i += 256) {
        float v = bda[i];
#pragma unroll
        for (int s = 0; s < HSL; s++) v += g_partH[(long long)s * Bq * HP + b * HP + i];
        sh_att2[i] = v;
        sh_w[i] = wfull[i];
    }
    __syncthreads();

    int wrp = tid >> 5, lane = tid & 31;
    const __half* A1 = g_att1h + (long long)b * Pq * ADq;
    for (int p = wrp; p < Pq; p += 8) {
        const uint4* row = (const uint4*)(A1 + p * ADq);
        float s = 0.0f;
#pragma unroll
        for (int j = 0; j < 2; j++) {
            int i8 = j * 32 + lane;
            uint4 v = row[i8];
            const __half2* h2 = (const __half2*)&v;
            int a0 = i8 * 8;
#pragma unroll
            for (int q = 0; q < 4; q++) {
                float2 f = __half22float2(h2[q]);
                int a = a0 + q * 2;
                s += fmaxf(f.x + sh_att2[a], 0.f) * sh_w[a]
                   + fmaxf(f.y + sh_att2[a + 1], 0.f) * sh_w[a + 1];
            }
        }
        for (int o = 16; o > 0; o >>= 1) s += __shfl_down_sync(0xffffffffu, s, o);
        if (lane == 0) sh_e[p] = s + bfull[0];
    }
    __syncthreads();

    float mval = -1e30f;
    if (tid < Pq) mval = sh_e[tid];
    for (int o = 16; o > 0; o >>= 1) mval = fmaxf(mval, __shfl_down_sync(0xffffffffu, mval, o));
    if (lane == 0) red[wrp] = mval;
    __syncthreads();
    if (tid == 0) {
        float m2 = red[0];
        for (int i = 1; i < 8; i++) m2 = fmaxf(m2, red[i]);
        red[0] = m2;
    }
    __syncthreads();
    float mx = red[0];
    __syncthreads();

    float ex = 0.0f;
    if (tid < Pq) ex = expf(sh_e[tid] - mx);
    float se = ex;
    for (int o = 16; o > 0; o >>= 1) se += __shfl_down_sync(0xffffffffu, se, o);
    if (lane == 0) red[wrp] = se;
    __syncthreads();
    if (tid == 0) {
        float s2 = 0.0f;
        for (int i = 0; i < 8; i++) s2 += red[i];
        red[0] = s2;
    }
    __syncthreads();
    float ssum = red[0];
    __syncthreads();

    float mk = (g_declen[b] > t) ? 1.0f : 0.0f;
    if (tid < Pq) {
        float al = ex / ssum;
        sh_e[tid] = al;
        if (hv == 0)
            out[OUT_ALPHAS + (long long)b * TD * Pq + (long long)t * Pq + tid] = al * mk;
    }
    __syncthreads();

    // awe: p-split halves, 16B loads, 8 channels/thread over all 2048
    int ch0 = tid * 8;
    const uint4* eb4 = (const uint4*)(g_eosh + (long long)b * Pq * EDq + ch0);
    float acc[8] = {};
    int p0 = hv * 98;
#pragma unroll 7
    for (int j = 0; j < 98; j++) {
        int p = p0 + j;
        float a = sh_e[p];
        uint4 v = eb4[(long long)p * 256];
        const __half2* h2 = (const __half2*)&v;
#pragma unroll
        for (int q = 0; q < 4; q++) {
            float2 f = __half22float2(h2[q]);
            acc[q * 2]     += a * f.x;
            acc[q * 2 + 1] += a * f.y;
        }
    }
    float* ap = g_awepart + ((long long)hv * Bq + b) * EDq + ch0;
    *(float4*)&ap[0] = make_float4(acc[0], acc[1], acc[2], acc[3]);
    *(float4*)&ap[4] = make_float4(acc[4], acc[5], acc[6], acc[7]);

    __threadfence();
    __syncthreads();
    if (tid == 0) {
        unsigned old = atomicAdd(&g_cntA[b], 1u);
        *s_last = ((old & 1u) == 1u) ? 1u : 0u;
    }
    __syncthreads();
    if (*s_last) {
        __threadfence();
        const float* a0p = g_awepart + (long long)b * EDq + ch0;
        const float* a1p = g_awepart + ((long long)Bq + b) * EDq + ch0;
        float4 u0 = *(const float4*)&a0p[0];
        float4 u1 = *(const float4*)&a0p[4];
        float4 v0 = *(const float4*)&a1p[0];
        float4 v1 = *(const float4*)&a1p[4];
        float aw[8] = { u0.x + v0.x, u0.y + v0.y, u0.z + v0.z, u0.w + v0.w,
                        u1.x + v1.x, u1.y + v1.y, u1.z + v1.z, u1.w + v1.w };
        float g[8];
#pragma unroll
        for (int q = 0; q < 2; q++) {
            float4 gs = make_float4(0.f, 0.f, 0.f, 0.f);
#pragma unroll
            for (int s = 0; s < HSL; s++) {
                float4 gv = *(const float4*)&g_partH[(long long)s * Bq * HP + b * HP + ADq + ch0 + q * 4];
                gs.x += gv.x; gs.y += gv.y; gs.z += gv.z; gs.w += gv.w;
            }
            float4 bb = *(const float4*)&bfb[ch0 + q * 4];
            g[q * 4 + 0] = sigf(gs.x + bb.x);
            g[q * 4 + 1] = sigf(gs.y + bb.y);
            g[q * 4 + 2] = sigf(gs.z + bb.z);
            g[q * 4 + 3] = sigf(gs.w + bb.w);
        }
        __half2 h0 = __floats2half2_rn(g[0] * aw[0], g[1] * aw[1]);
        __half2 h1 = __floats2half2_rn(g[2] * aw[2], g[3] * aw[3]);
        __half2 h2 = __floats2half2_rn(g[4] * aw[4], g[5] * aw[5]);
        __half2 h3 = __floats2half2_rn(g[6] * aw[6], g[7] * aw[7]);
        uint2 st0, st1;
        st0.x = *(unsigned*)&h0; st0.y = *(unsigned*)&h1;
        st1.x = *(unsigned*)&h2; st1.y = *(unsigned*)&h3;
        *(uint2*)&g_xcath[b * KPAD + Eq + ch0]     = st0;
        *(uint2*)&g_xcath[b * KPAD + Eq + ch0 + 4] = st1;
    }
}

__device__ void preds_reduce_block(int b, int tp, const float* __restrict__ bfc,
                                   float* __restrict__ out)
{
    int tid = threadIdx.x;
    float mk = (g_declen[b] > tp) ? 1.0f : 0.0f;
    for (int n = tid; n < Vq; n += 256) {
        float v = bfc[n];
#pragma unroll
        for (int s = 0; s < 4; s++) v += g_partP[(long long)s * Bq * VPAD + b * VPAD + n];
        out[OUT_PRED + (long long)b * TD * Vq + (long long)tp * Vq + n] = v * mk;
    }
}

__global__ void __launch_bounds__(256, 2)
k_loop(const float* __restrict__ emb, const float* __restrict__ wfull,
       const float* __restrict__ bfull, const float* __restrict__ bda,
       const float* __restrict__ bfb, const float* __restrict__ bfc,
       float* __restrict__ out)
{
    __shared__ float SH[3072];
    __shared__ unsigned s_last;
    int bid = blockIdx.x;

    for (int t = 0; t <= TD; t++) {
        // ---- phase 1: hproj wmma (0-159) | preds(t-1) wmma (160-191) | staging (192-255) ----
        if (t < TD && bid < 160) {
            int nt = bid >> 3, s = bid & 7;
            gemm_wmma(g_hh, DDq, g_whcatH, HP, g_partH + (long long)s * Bq * HP, HP,
                      nt * 128, s * 64, s * 64 + 64, SH);
        } else if (t > 0 && bid >= 160 && bid < 192) {
            int q = bid - 160;
            int s = q >> 3, nt = q & 7;
            gemm_wmma(g_hh, DDq, g_wfch, VPAD, g_partP + (long long)s * Bq * VPAD, VPAD,
                      nt * 128, s * 128, s * 128 + 128, SH);
        } else if (t < TD && bid >= 192 && bid < 256) {
            int b = bid - 192;
            int tok = g_caps[b * Tq + t];
            for (int i = threadIdx.x; i < Eq; i += 256)
                g_xcath[b * KPAD + i] = __float2half(emb[(long long)tok * Eq + i]);
            for (int i = threadIdx.x; i < DDq; i += 256)
                g_xcath[b * KPAD + 2348 + i] = g_hh[b * DDq + i];
        }
        gridbar();

        // ---- phase 2: attn + awe pairs (0-127) | preds reduce (128-191) ----
        if (bid < 128) {
            if (t < TD) attn_awe_pair(bid, t, wfull, bfull, bda, bfb, out, SH, &s_last);
        } else if (t > 0 && bid < 192) {
            preds_reduce_block(bid - 128, t - 1, bfc, out);
        }
        gridbar();

        if (t == TD) break;

        // ---- phase 3: gates wmma (16 nt x 9 K-slices) + fused cell (last arriver) ----
        if (bid < 144) {
            int nt = bid / 9, s = bid % 9;
            int k0 = s * 320;
            int k1 = (s == 8) ? KPAD : (k0 + 320);
            gemm_wmma(g_xcath, KPAD, g_wcath, G4, g_partG + (long long)s * Bq * G4, G4,
                      nt * 128, k0, k1, SH);
            __syncthreads();
            if (threadIdx.x == 0) {
                asm volatile("fence.acq_rel.gpu;" ::: "memory");
                unsigned old = atomicAdd(&g_cntG[nt], 1u);
                s_last = ((old % 9u) == 8u) ? 1u : 0u;
            }
            __syncthreads();
            if (s_last) {
                asm volatile("fence.acq_rel.gpu;" ::: "memory");
                for (int item = threadIdx.x; item < 2048; item += 256) {
                    int b = item >> 5, dd = item & 31;
                    int col = nt * 128 + dd * 4;
                    float4 a = *(const float4*)&g_biasg[col];
#pragma unroll
                    for (int s2 = 0; s2 < 9; s2++) {
                        float4 v = *(const float4*)&g_partG[(long long)s2 * Bq * G4 + b * G4 + col];
                        a.x += v.x; a.y += v.y; a.z += v.z; a.w += v.w;
                    }
                    int d = nt * 32 + dd;
                    float co = g_c[b * DDq + d], ho = g_h[b * DDq + d];
                    float cn = sigf(a.y) * co + sigf(a.x) * tanhf(a.z);
                    float hn = sigf(a.w) * tanhf(cn);
                    bool mk = (g_declen[b] > t);
                    float hf = mk ? hn : ho;
                    g_h[b * DDq + d] = hf;
                    g_hh[b * DDq + d] = __float2half(hf);
                    g_c[b * DDq + d] = mk ? cn : co;
                }
            }
        }
        gridbar();
    }
}

// =================================================================================
extern "C" void kernel_launch(void* const* d_in, const int* in_sizes, int n_in,
                              void* d_out, int out_size)
{
    const float* eo    = (const float*)d_in[0];
    const int*   caps  = (const int*)  d_in[1];
    const int*   lens  = (const int*)  d_in[2];
    const float* emb   = (const float*)d_in[3];
    const float* Wea   = (const float*)d_in[4];
    const float* bea   = (const float*)d_in[5];
    const float* Wda   = (const float*)d_in[6];
    const float* bda   = (const float*)d_in[7];
    const float* wfull = (const float*)d_in[8];
    const float* bfull = (const float*)d_in[9];
    const float* Wih0  = (const float*)d_in[10];
    const float* bih0  = (const float*)d_in[11];
    const float* Wic0  = (const float*)d_in[12];
    const float* bic0  = (const float*)d_in[13];
    const float* Wfb   = (const float*)d_in[14];
    const float* bfb   = (const float*)d_in[15];
    const float* WIH   = (const float*)d_in[16];
    const float* bIH   = (const float*)d_in[17];
    const float* WHH   = (const float*)d_in[18];
    const float* bHH   = (const float*)d_in[19];
    const float* Wfc   = (const float*)d_in[20];
    const float* bfc   = (const float*)d_in[21];
    float* out = (float*)d_out;

    {
        long long tot = (long long)KCAT * G4 + (long long)DDq * HP
                      + (long long)EDq * ADq + (long long)DDq * VPAD;
        int nb = (int)((tot + 1023) / 1024);
        k_prep<<<nb, 1024>>>(lens, caps, out, WIH, WHH, bIH, bHH, Wda, Wfb, Wea, Wfc);
    }
    k_gather<<<Bq * Pq, 256>>>(eo);
    k_setup2<<<NBLK, 256>>>(Wih0, bih0, Wic0, bic0, bea);
    k_loop<<<NBLK, 256>>>(emb, wfull, bfull, bda, bfb, bfc, out);
}

// round 15
// speedup vs baseline: 1.0604x; 1.0604x over previous
#include <cuda_runtime.h>
#include <cuda_fp16.h>
#include <mma.h>
#include <math.h>

using namespace nvcuda;

#define Bq   64
#define Pq   196
#define EDq  2048
#define ADq  512
#define DDq  512
#define Eq   300
#define Vq   1000
#define VPAD 1024
#define Tq   96
#define TD   95
#define KCAT 2860   // (E + ED) + DD = 2348 + 512
#define KPAD 2864   // KCAT padded to multiple of 16
#define G4   2048   // 4*DD
#define HP   2560   // [W_dec_att | W_fbeta] width
#define NBLK 296
#define ASL  8      // att2 K-slices (64 wide)
#define BSL  4      // gate K-slices (128 wide)

// output layout (flattened fp32, reference-return order)
#define OUT_PRED    0LL
#define OUT_CAPS    6080000LL
#define OUT_DECLEN  6086144LL
#define OUT_ALPHAS  6086208LL
#define OUT_SORTIND 7277888LL

// ---------------- scratch ----------------
__device__ int   g_sortind[Bq];
__device__ int   g_declen[Bq];
__device__ int   g_caps[Bq * Tq];
__device__ __half g_eosh[(long long)Bq * Pq * EDq];      // fp16 sorted eo (~51MB)
__device__ float g_att1f[(long long)Bq * Pq * ADq];      // fp32 att1 staging (setup)
__device__ __half g_att1h[(long long)Bq * Pq * ADq];     // fp16 att1 + bias (loop)
__device__ float g_meaneo[Bq * EDq];
__device__ float g_h[Bq * DDq];
__device__ __half g_hh[Bq * DDq];                        // fp16 h (wmma A operand)
__device__ float g_c[Bq * DDq];
__device__ __half g_xcath[Bq * KPAD];                    // fp16 [emb | gate*awe | h | 0pad]
__device__ __half g_wcath[(long long)KPAD * G4];         // fp16 gates W, INTERLEAVED cols (d*4+gate)
__device__ __half g_whcatH[(long long)DDq * HP];         // fp16 [W_dec_att | W_fbeta]
__device__ __half g_weah[(long long)EDq * ADq];          // fp16 W_enc_att
__device__ __half g_wfch[(long long)DDq * VPAD];         // fp16 W_fc, cols padded to 1024
__device__ float g_biasg[G4];                            // (b_ih + b_hh), interleaved
__device__ float g_part[16LL * Bq * DDq];                // setup split-K scratch
__device__ float g_partA[(long long)ASL * Bq * ADq];     // att2 slices
__device__ float g_partB[(long long)BSL * Bq * G4];      // gate slices
__device__ float g_partP[4LL * Bq * VPAD];               // preds slices
__device__ float g_partG[9LL * Bq * G4];                 // gates slices (interleaved cols)
__device__ float g_awepart[2LL * Bq * EDq];              // awe p-split partials
__device__ unsigned g_barcnt;                            // zero-init, monotonic
__device__ unsigned g_cntG[16];                          // gates n-tile arrival counters
__device__ unsigned g_cntA[Bq];                          // awe pair arrival counters
__device__ unsigned g_cntB;                              // gate GEMM arrivals (reset at t=0)

__device__ __forceinline__ float sigf(float x) { return 1.0f / (1.0f + expf(-x)); }

// ---------------- grid barrier (round-9 proven) ----------------
__device__ __forceinline__ void gridbar()
{
    __syncthreads();
    if (threadIdx.x == 0) {
        asm volatile("fence.acq_rel.gpu;" ::: "memory");
        unsigned old = atomicAdd(&g_barcnt, 1u);
        unsigned target = old - (old % (unsigned)NBLK) + (unsigned)NBLK;
        unsigned cur;
        do {
            asm volatile("ld.acquire.gpu.u32 %0, [%1];" : "=r"(cur) : "l"(&g_barcnt));
        } while ((int)(cur - target) < 0);
    }
    __syncthreads();
}

// =============== setup kernel 1: sort + all weight conversions ===============
__global__ void k_prep(const int* __restrict__ lens, const int* __restrict__ caps,
                       float* __restrict__ out,
                       const float* __restrict__ Wih, const float* __restrict__ Whh,
                       const float* __restrict__ bih, const float* __restrict__ bhh,
                       const float* __restrict__ Wda, const float* __restrict__ Wfb,
                       const float* __restrict__ Wea, const float* __restrict__ Wfc)
{
    if (blockIdx.x == 0) {
        int i = threadIdx.x;
        if (i < Bq) {
            int li = lens[i];
            int r = 0;
            for (int j = 0; j < Bq; j++) {
                int lj = lens[j];
                if (lj > li || (lj == li && j < i)) r++;
            }
            g_sortind[r] = i;
        }
        __syncthreads();
        if (i < Bq) {
            int src = g_sortind[i];
            int dl = lens[src] - 1;
            g_declen[i] = dl;
            out[OUT_DECLEN + i]  = (float)dl;
            out[OUT_SORTIND + i] = (float)src;
            for (int tt = 0; tt < Tq; tt++) {
                int v = caps[src * Tq + tt];
                g_caps[i * Tq + tt] = v;
                out[OUT_CAPS + i * Tq + tt] = (float)v;
            }
        }
    }
    long long idx = (long long)blockIdx.x * blockDim.x + threadIdx.x;
    long long n1 = (long long)KCAT * G4;
    long long n2 = (long long)DDq * HP;
    long long n3 = (long long)EDq * ADq;
    long long n4 = (long long)DDq * VPAD;
    if (idx < n1) {
        int row = (int)(idx / G4), ncol = (int)(idx % G4);
        int d = ncol >> 2, gate = ncol & 3;
        int scol = gate * 512 + d;
        float v = (row < 2348) ? Wih[(long long)row * G4 + scol]
                               : Whh[(long long)(row - 2348) * G4 + scol];
        g_wcath[idx] = __float2half(v);
    } else if (idx < n1 + n2) {
        long long idx2 = idx - n1;
        int row = (int)(idx2 / HP), col = (int)(idx2 % HP);
        float v = (col < ADq) ? Wda[(long long)row * ADq + col]
                              : Wfb[(long long)row * EDq + (col - ADq)];
        g_whcatH[idx2] = __float2half(v);
    } else if (idx < n1 + n2 + n3) {
        long long idx3 = idx - n1 - n2;
        g_weah[idx3] = __float2half(Wea[idx3]);
    } else if (idx < n1 + n2 + n3 + n4) {
        long long idx4 = idx - n1 - n2 - n3;
        int row = (int)(idx4 >> 10), col = (int)(idx4 & (VPAD - 1));
        float v = (col < Vq) ? Wfc[(long long)row * Vq + col] : 0.0f;
        g_wfch[idx4] = __float2half(v);
    }
    if (idx < G4) {
        int d = (int)(idx >> 2), gate = (int)(idx & 3);
        int scol = gate * 512 + d;
        g_biasg[idx] = bih[scol] + bhh[scol];
    }
}

// =============== setup kernel 2: gather encoder_out (sorted, fp16) ===============
__global__ void k_gather(const float* __restrict__ eo)
{
    int bp = blockIdx.x;
    int b = bp / Pq, p = bp % Pq;
    int src = g_sortind[b];
    const float4* s = (const float4*)(eo + ((long long)(src * Pq + p)) * EDq);
    __half2* dh = (__half2*)(g_eosh + (long long)bp * EDq);
    for (int i = threadIdx.x; i < EDq / 4; i += blockDim.x) {
        float4 v = s[i];
        dh[i * 2]     = __floats2half2_rn(v.x, v.y);
        dh[i * 2 + 1] = __floats2half2_rn(v.z, v.w);
    }
}

// ---------------- fp16 wmma GEMM device: C[64, col0:+128] = A @ B ----------------
__device__ __forceinline__ void gemm_wmma(const __half* __restrict__ A, int lda,
    const __half* __restrict__ B, int ldb, float* __restrict__ C, int ldc,
    int col0, int k0, int k1, float* SHf)
{
    __half* As = (__half*)SHf;          // [64][16]
    __half* Bs = As + 64 * 16;          // [16][128]
    int tid = threadIdx.x;
    int wid = tid >> 5;
    int mt = wid >> 1;
    int nh = (wid & 1) * 64;

    wmma::fragment<wmma::accumulator, 16, 16, 16, float> acc[4];
#pragma unroll
    for (int j = 0; j < 4; j++) wmma::fill_fragment(acc[j], 0.0f);

    int arow = tid >> 1;
    int acol8 = (tid & 1) * 8;
    int bk = tid >> 4;
    int bn8 = (tid & 15) * 8;

    uint4 pa, pb;
    if (tid < 128) pa = *(const uint4*)&A[(long long)arow * lda + k0 + acol8];
    pb = *(const uint4*)&B[(long long)(k0 + bk) * ldb + col0 + bn8];

    for (int kb = k0; kb < k1; kb += 16) {
        if (tid < 128) *(uint4*)&As[arow * 16 + acol8] = pa;
        *(uint4*)&Bs[bk * 128 + bn8] = pb;
        __syncthreads();

        int kn = kb + 16;
        if (kn < k1) {
            if (tid < 128) pa = *(const uint4*)&A[(long long)arow * lda + kn + acol8];
            pb = *(const uint4*)&B[(long long)(kn + bk) * ldb + col0 + bn8];
        }

        wmma::fragment<wmma::matrix_a, 16, 16, 16, __half, wmma::row_major> af;
        wmma::load_matrix_sync(af, As + mt * 16 * 16, 16);
#pragma unroll
        for (int j = 0; j < 4; j++) {
            wmma::fragment<wmma::matrix_b, 16, 16, 16, __half, wmma::row_major> bf;
            wmma::load_matrix_sync(bf, Bs + nh + j * 16, 128);
            wmma::mma_sync(acc[j], af, bf, acc[j]);
        }
        __syncthreads();
    }

#pragma unroll
    for (int j = 0; j < 4; j++)
        wmma::store_matrix_sync(C + (long long)(mt * 16) * ldc + col0 + nh + j * 16,
                                acc[j], ldc, wmma::mem_row_major);
}

// ---------------- fp32 64x128 GEMM device (h0/c0 setup only) ----------------
__device__ __forceinline__ void gemm64x128(const float* __restrict__ A, int lda,
    const float* __restrict__ B, int ldb, float* __restrict__ C, int ldc,
    int col0, int N, int k0, int k1, float* SH)
{
    float* As = SH;
    float* Bs = SH + 1024;
    int tid = threadIdx.x;
    int tx = tid & 31, ty = tid >> 5;
    float acc[8][4] = {};

    int am  = tid & 63;
    int akq = (tid >> 6) << 2;
    int bkk0 = tid >> 5;
    int bkk1 = bkk0 + 8;
    int bn   = (tid & 31) << 2;

    for (int kb = k0; kb < k1; kb += 16) {
        {
            int kg = kb + akq;
            float4 pa = *(const float4*)&A[(long long)am * lda + kg];
            As[(akq + 0) * 64 + am] = pa.x;
            As[(akq + 1) * 64 + am] = pa.y;
            As[(akq + 2) * 64 + am] = pa.z;
            As[(akq + 3) * 64 + am] = pa.w;
            int kgb0 = kb + bkk0, kgb1 = kb + bkk1, ng = col0 + bn;
            float4 pb0 = make_float4(0.f,0.f,0.f,0.f), pb1 = make_float4(0.f,0.f,0.f,0.f);
            if (ng + 3 < N) {
                pb0 = *(const float4*)&B[(long long)kgb0 * ldb + ng];
                pb1 = *(const float4*)&B[(long long)kgb1 * ldb + ng];
            } else {
                for (int j = 0; j < 4; j++) if (ng + j < N) {
                    ((float*)&pb0)[j] = B[(long long)kgb0 * ldb + ng + j];
                    ((float*)&pb1)[j] = B[(long long)kgb1 * ldb + ng + j];
                }
            }
            *(float4*)&Bs[bkk0 * 128 + bn] = pb0;
            *(float4*)&Bs[bkk1 * 128 + bn] = pb1;
        }
        __syncthreads();
#pragma unroll
        for (int kk = 0; kk < 16; kk++) {
            float a0[4], a1[4], bb[4];
            *(float4*)&a0[0] = *(const float4*)&As[kk * 64 + ty * 8];
            *(float4*)&a1[0] = *(const float4*)&As[kk * 64 + ty * 8 + 4];
            *(float4*)&bb[0] = *(const float4*)&Bs[kk * 128 + tx * 4];
#pragma unroll
            for (int i = 0; i < 4; i++)
#pragma unroll
                for (int j = 0; j < 4; j++) {
                    acc[i][j]     += a0[i] * bb[j];
                    acc[i + 4][j] += a1[i] * bb[j];
                }
        }
        __syncthreads();
    }

#pragma unroll
    for (int i = 0; i < 8; i++) {
        int m = ty * 8 + i;
#pragma unroll
        for (int j = 0; j < 4; j++) {
            int n = col0 + tx * 4 + j;
            if (n < N) C[(long long)m * ldc + n] = acc[i][j];
        }
    }
}

// =============== setup kernel 3: mean, h0/c0, att1 (persistent) ===============
__global__ void __launch_bounds__(256, 2)
k_setup2(const float* __restrict__ Wih0, const float* __restrict__ bih0,
         const float* __restrict__ Wic0, const float* __restrict__ bic0,
         const float* __restrict__ bea)
{
    __shared__ float SH[3072];
    int bid = blockIdx.x;
    int tid = threadIdx.x;

    for (int task = bid; task < 512; task += NBLK) {
        int b = task >> 3, chunk = task & 7;
        int e = chunk * 256 + tid;
        float s = 0.0f;
        const __half* base = g_eosh + (long long)b * Pq * EDq + e;
        for (int p = 0; p < Pq; p++) s += __half2float(base[(long long)p * EDq]);
        g_meaneo[b * EDq + e] = s * (1.0f / (float)Pq);
    }
    gridbar();

    for (int task = bid; task < 784 + 64; task += NBLK) {
        if (task < 784) {
            int mrow = task >> 2, nt = task & 3;
            gemm_wmma(g_eosh + (long long)mrow * 64 * EDq, EDq, g_weah, ADq,
                      g_att1f + (long long)mrow * 64 * ADq, ADq, nt * 128, 0, EDq, SH);
        } else {
            int t2 = task - 784;
            int w = t2 >> 5;
            int s = (t2 >> 2) & 7;
            int nt = t2 & 3;
            const float* W = w ? Wic0 : Wih0;
            gemm64x128(g_meaneo, EDq, W, DDq,
                       g_part + (long long)(w * 8 + s) * Bq * DDq, DDq,
                       nt * 128, DDq, s * 256, s * 256 + 256, SH);
        }
    }
    gridbar();

    for (long long idx = (long long)bid * 256 + tid; idx < 2LL * Bq * DDq;
         idx += (long long)NBLK * 256) {
        int w = (int)(idx >> 15);
        int i = (int)(idx & 32767);
        int n = i & (DDq - 1);
        float v = w ? bic0[n] : bih0[n];
#pragma unroll
        for (int s = 0; s < 8; s++) v += g_part[(long long)(w * 8 + s) * Bq * DDq + i];
        if (w == 0) { g_h[i] = v; g_hh[i] = __float2half(v); }
        else g_c[i] = v;
    }
    for (long long i = (long long)bid * 256 + tid; i < (long long)Bq * Pq * ADq;
         i += (long long)NBLK * 256)
        g_att1h[i] = __float2half(g_att1f[i] + bea[i & (ADq - 1)]);
}

// ================= persistent loop kernel =================

// fused attention + p-split awe; 2 blocks per batch.
// att2 from g_partA (8 slices); gate from g_partB (4 slices) guarded by g_cntB.
__device__ void attn_awe_pair(int bid, int t, const float* __restrict__ wfull,
                              const float* __restrict__ bfull,
                              const float* __restrict__ bda,
                              const float* __restrict__ bfb,
                              float* __restrict__ out, float* SH,
                              unsigned* s_last)
{
    int b = bid >> 1, hv = bid & 1;
    float* sh_att2 = SH;
    float* sh_w    = SH + 512;
    float* sh_e    = SH + 1024;
    float* red     = SH + 1248;
    int tid = threadIdx.x;

    for (int i = tid; i < ADq; i += 256) {
        float v = bda[i];
#pragma unroll
        for (int s = 0; s < ASL; s++) v += g_partA[(long long)s * Bq * ADq + b * ADq + i];
        sh_att2[i] = v;
        sh_w[i] = wfull[i];
    }
    __syncthreads();

    int wrp = tid >> 5, lane = tid & 31;
    const __half* A1 = g_att1h + (long long)b * Pq * ADq;
    for (int p = wrp; p < Pq; p += 8) {
        const uint4* row = (const uint4*)(A1 + p * ADq);
        float s = 0.0f;
#pragma unroll
        for (int j = 0; j < 2; j++) {
            int i8 = j * 32 + lane;
            uint4 v = row[i8];
            const __half2* h2 = (const __half2*)&v;
            int a0 = i8 * 8;
#pragma unroll
            for (int q = 0; q < 4; q++) {
                float2 f = __half22float2(h2[q]);
                int a = a0 + q * 2;
                s += fmaxf(f.x + sh_att2[a], 0.f) * sh_w[a]
                   + fmaxf(f.y + sh_att2[a + 1], 0.f) * sh_w[a + 1];
            }
        }
        for (int o = 16; o > 0; o >>= 1) s += __shfl_down_sync(0xffffffffu, s, o);
        if (lane == 0) sh_e[p] = s + bfull[0];
    }
    __syncthreads();

    float mval = -1e30f;
    if (tid < Pq) mval = sh_e[tid];
    for (int o = 16; o > 0; o >>= 1) mval = fmaxf(mval, __shfl_down_sync(0xffffffffu, mval, o));
    if (lane == 0) red[wrp] = mval;
    __syncthreads();
    if (tid == 0) {
        float m2 = red[0];
        for (int i = 1; i < 8; i++) m2 = fmaxf(m2, red[i]);
        red[0] = m2;
    }
    __syncthreads();
    float mx = red[0];
    __syncthreads();

    float ex = 0.0f;
    if (tid < Pq) ex = expf(sh_e[tid] - mx);
    float se = ex;
    for (int o = 16; o > 0; o >>= 1) se += __shfl_down_sync(0xffffffffu, se, o);
    if (lane == 0) red[wrp] = se;
    __syncthreads();
    if (tid == 0) {
        float s2 = 0.0f;
        for (int i = 0; i < 8; i++) s2 += red[i];
        red[0] = s2;
    }
    __syncthreads();
    float ssum = red[0];
    __syncthreads();

    float mk = (g_declen[b] > t) ? 1.0f : 0.0f;
    if (tid < Pq) {
        float al = ex / ssum;
        sh_e[tid] = al;
        if (hv == 0)
            out[OUT_ALPHAS + (long long)b * TD * Pq + (long long)t * Pq + tid] = al * mk;
    }
    __syncthreads();

    // awe: p-split halves, 16B loads, 8 channels/thread over all 2048
    int ch0 = tid * 8;
    const uint4* eb4 = (const uint4*)(g_eosh + (long long)b * Pq * EDq + ch0);
    float acc[8] = {};
    int p0 = hv * 98;
#pragma unroll 7
    for (int j = 0; j < 98; j++) {
        int p = p0 + j;
        float a = sh_e[p];
        uint4 v = eb4[(long long)p * 256];
        const __half2* h2 = (const __half2*)&v;
#pragma unroll
        for (int q = 0; q < 4; q++) {
            float2 f = __half22float2(h2[q]);
            acc[q * 2]     += a * f.x;
            acc[q * 2 + 1] += a * f.y;
        }
    }
    float* ap = g_awepart + ((long long)hv * Bq + b) * EDq + ch0;
    *(float4*)&ap[0] = make_float4(acc[0], acc[1], acc[2], acc[3]);
    *(float4*)&ap[4] = make_float4(acc[4], acc[5], acc[6], acc[7]);

    __threadfence();
    __syncthreads();
    if (tid == 0) {
        unsigned old = atomicAdd(&g_cntA[b], 1u);
        *s_last = ((old & 1u) == 1u) ? 1u : 0u;
    }
    __syncthreads();

    // wait for gate GEMM of this step (concurrent in phase 2); usually already done
    if (tid == 0) {
        unsigned tgt = 64u * ((unsigned)t + 1u);
        unsigned cur;
        do {
            asm volatile("ld.acquire.gpu.u32 %0, [%1];" : "=r"(cur) : "l"(&g_cntB));
        } while (cur < tgt);
    }
    __syncthreads();

    if (*s_last) {
        __threadfence();
        const float* a0p = g_awepart + (long long)b * EDq + ch0;
        const float* a1p = g_awepart + ((long long)Bq + b) * EDq + ch0;
        float4 u0 = *(const float4*)&a0p[0];
        float4 u1 = *(const float4*)&a0p[4];
        float4 v0 = *(const float4*)&a1p[0];
        float4 v1 = *(const float4*)&a1p[4];
        float aw[8] = { u0.x + v0.x, u0.y + v0.y, u0.z + v0.z, u0.w + v0.w,
                        u1.x + v1.x, u1.y + v1.y, u1.z + v1.z, u1.w + v1.w };
        float g[8];
#pragma unroll
        for (int q = 0; q < 2; q++) {
            float4 gs = make_float4(0.f, 0.f, 0.f, 0.f);
#pragma unroll
            for (int s = 0; s < BSL; s++) {
                float4 gv = *(const float4*)&g_partB[(long long)s * Bq * G4 + b * G4 + ch0 + q * 4];
                gs.x += gv.x; gs.y += gv.y; gs.z += gv.z; gs.w += gv.w;
            }
            float4 bb = *(const float4*)&bfb[ch0 + q * 4];
            g[q * 4 + 0] = sigf(gs.x + bb.x);
            g[q * 4 + 1] = sigf(gs.y + bb.y);
            g[q * 4 + 2] = sigf(gs.z + bb.z);
            g[q * 4 + 3] = sigf(gs.w + bb.w);
        }
        __half2 h0 = __floats2half2_rn(g[0] * aw[0], g[1] * aw[1]);
        __half2 h1 = __floats2half2_rn(g[2] * aw[2], g[3] * aw[3]);
        __half2 h2 = __floats2half2_rn(g[4] * aw[4], g[5] * aw[5]);
        __half2 h3 = __floats2half2_rn(g[6] * aw[6], g[7] * aw[7]);
        uint2 st0, st1;
        st0.x = *(unsigned*)&h0; st0.y = *(unsigned*)&h1;
        st1.x = *(unsigned*)&h2; st1.y = *(unsigned*)&h3;
        *(uint2*)&g_xcath[b * KPAD + Eq + ch0]     = st0;
        *(uint2*)&g_xcath[b * KPAD + Eq + ch0 + 4] = st1;
    }
}

__device__ void preds_reduce_block(int b, int tp, const float* __restrict__ bfc,
                                   float* __restrict__ out)
{
    int tid = threadIdx.x;
    float mk = (g_declen[b] > tp) ? 1.0f : 0.0f;
    for (int n = tid; n < Vq; n += 256) {
        float v = bfc[n];
#pragma unroll
        for (int s = 0; s < 4; s++) v += g_partP[(long long)s * Bq * VPAD + b * VPAD + n];
        out[OUT_PRED + (long long)b * TD * Vq + (long long)tp * Vq + n] = v * mk;
    }
}

__global__ void __launch_bounds__(256, 2)
k_loop(const float* __restrict__ emb, const float* __restrict__ wfull,
       const float* __restrict__ bfull, const float* __restrict__ bda,
       const float* __restrict__ bfb, const float* __restrict__ bfc,
       float* __restrict__ out)
{
    __shared__ float SH[3072];
    __shared__ unsigned s_last;
    int bid = blockIdx.x;

    for (int t = 0; t <= TD; t++) {
        // ---- phase 1: att2 (0-31) | preds wmma (32-63) | staging (64-127) | cntB reset ----
        if (t < TD && bid < 32) {
            int nt = bid >> 3, s = bid & 7;
            gemm_wmma(g_hh, DDq, g_whcatH, HP, g_partA + (long long)s * Bq * ADq, ADq,
                      nt * 128, s * 64, s * 64 + 64, SH);
        } else if (t > 0 && bid >= 32 && bid < 64) {
            int q = bid - 32;
            int s = q >> 3, nt = q & 7;
            gemm_wmma(g_hh, DDq, g_wfch, VPAD, g_partP + (long long)s * Bq * VPAD, VPAD,
                      nt * 128, s * 128, s * 128 + 128, SH);
        } else if (t < TD && bid >= 64 && bid < 128) {
            int b = bid - 64;
            int tok = g_caps[b * Tq + t];
            for (int i = threadIdx.x; i < Eq; i += 256)
                g_xcath[b * KPAD + i] = __float2half(emb[(long long)tok * Eq + i]);
            for (int i = threadIdx.x; i < DDq; i += 256)
                g_xcath[b * KPAD + 2348 + i] = g_hh[b * DDq + i];
        } else if (t == 0 && bid == 255) {
            if (threadIdx.x == 0) g_cntB = 0u;
            __threadfence();
        }
        gridbar();

        // ---- phase 2: attn+awe (0-127) || gate GEMM (128-191) ----
        if (t < TD && bid < 128) {
            attn_awe_pair(bid, t, wfull, bfull, bda, bfb, out, SH, &s_last);
        } else if (t < TD && bid >= 128 && bid < 192) {
            int q = bid - 128;
            int nt = q >> 2, s = q & 3;                       // nt 0..15, s 0..3
            gemm_wmma(g_hh, DDq, g_whcatH, HP,
                      g_partB + (long long)s * Bq * G4 - 512, G4,
                      512 + nt * 128, s * 128, s * 128 + 128, SH);
            __syncthreads();
            if (threadIdx.x == 0) {
                asm volatile("fence.acq_rel.gpu;" ::: "memory");
                atomicAdd(&g_cntB, 1u);
            }
        }
        gridbar();

        // ---- phase 3: gates wmma + fused cell (0-143) | preds reduce (144-207) ----
        if (t < TD && bid < 144) {
            int nt = bid / 9, s = bid % 9;
            int k0 = s * 320;
            int k1 = (s == 8) ? KPAD : (k0 + 320);
            gemm_wmma(g_xcath, KPAD, g_wcath, G4, g_partG + (long long)s * Bq * G4, G4,
                      nt * 128, k0, k1, SH);
            __syncthreads();
            if (threadIdx.x == 0) {
                asm volatile("fence.acq_rel.gpu;" ::: "memory");
                unsigned old = atomicAdd(&g_cntG[nt], 1u);
                s_last = ((old % 9u) == 8u) ? 1u : 0u;
            }
            __syncthreads();
            if (s_last) {
                asm volatile("fence.acq_rel.gpu;" ::: "memory");
                for (int item = threadIdx.x; item < 2048; item += 256) {
                    int b = item >> 5, dd = item & 31;
                    int col = nt * 128 + dd * 4;
                    float4 a = *(const float4*)&g_biasg[col];
#pragma unroll
                    for (int s2 = 0; s2 < 9; s2++) {
                        float4 v = *(const float4*)&g_partG[(long long)s2 * Bq * G4 + b * G4 + col];
                        a.x += v.x; a.y += v.y; a.z += v.z; a.w += v.w;
                    }
                    int d = nt * 32 + dd;
                    float co = g_c[b * DDq + d], ho = g_h[b * DDq + d];
                    float cn = sigf(a.y) * co + sigf(a.x) * tanhf(a.z);
                    float hn = sigf(a.w) * tanhf(cn);
                    bool mk = (g_declen[b] > t);
                    float hf = mk ? hn : ho;
                    g_h[b * DDq + d] = hf;
                    g_hh[b * DDq + d] = __float2half(hf);
                    g_c[b * DDq + d] = mk ? cn : co;
                }
            }
        } else if (t > 0 && bid >= 144 && bid < 208) {
            preds_reduce_block(bid - 144, t - 1, bfc, out);
        }
        if (t == TD) break;
        gridbar();
    }
}

// =================================================================================
extern "C" void kernel_launch(void* const* d_in, const int* in_sizes, int n_in,
                              void* d_out, int out_size)
{
    const float* eo    = (const float*)d_in[0];
    const int*   caps  = (const int*)  d_in[1];
    const int*   lens  = (const int*)  d_in[2];
    const float* emb   = (const float*)d_in[3];
    const float* Wea   = (const float*)d_in[4];
    const float* bea   = (const float*)d_in[5];
    const float* Wda   = (const float*)d_in[6];
    const float* bda   = (const float*)d_in[7];
    const float* wfull = (const float*)d_in[8];
    const float* bfull = (const float*)d_in[9];
    const float* Wih0  = (const float*)d_in[10];
    const float* bih0  = (const float*)d_in[11];
    const float* Wic0  = (const float*)d_in[12];
    const float* bic0  = (const float*)d_in[13];
    const float* Wfb   = (const float*)d_in[14];
    const float* bfb   = (const float*)d_in[15];
    const float* WIH   = (const float*)d_in[16];
    const float* bIH   = (const float*)d_in[17];
    const float* WHH   = (const float*)d_in[18];
    const float* bHH   = (const float*)d_in[19];
    const float* Wfc   = (const float*)d_in[20];
    const float* bfc   = (const float*)d_in[21];
    float* out = (float*)d_out;

    {
        long long tot = (long long)KCAT * G4 + (long long)DDq * HP
                      + (long long)EDq * ADq + (long long)DDq * VPAD;
        int nb = (int)((tot + 1023) / 1024);
        k_prep<<<nb, 1024>>>(lens, caps, out, WIH, WHH, bIH, bHH, Wda, Wfb, Wea, Wfc);
    }
    k_gather<<<Bq * Pq, 256>>>(eo);
    k_setup2<<<NBLK, 256>>>(Wih0, bih0, Wic0, bic0, bea);
    k_loop<<<NBLK, 256>>>(emb, wfull, bfull, bda, bfb, bfc, out);
}